// round 12
// baseline (speedup 1.0000x reference)
#include <cuda_runtime.h>
#include <cstdint>

#define T_STEPS 96
#define BATCH   32
#define HDIM    512
#define NCP     82
#define NBP     226
#define FEAT    2048
#define NBLK    128
#define LOG2E   1.4426950408889634f

#define OFF_OC 0u
#define OFF_OX 251904u
#define OFF_OY 946176u
#define OFF_OW 1640448u
#define OFF_OH 2334720u
#define OFF_OD 3028992u

// ---- static device scratch (no runtime allocation) ----
__device__ __align__(128) float g_k[BATCH * HDIM];
__device__ __align__(128) float g_v[BATCH * HDIM];
__device__ __align__(128) float g_kmin[BATCH];
__device__ __align__(128) float g_kmax[BATCH];
__device__ __align__(128) float g_Pclass[NCP * 1536];
__device__ __align__(128) float g_Pbin[4 * NBP * 1536];
__device__ __align__(128) float g_gi[(size_t)T_STEPS * BATCH * 1536];
__device__ __align__(128) float g_h[2 * BATCH * HDIM];
__device__ __align__(128) float g_Hall[(size_t)T_STEPS * BATCH * HDIM];
__device__ __align__(128) float g_Wcat[768 * 512];
__device__ __align__(128) float g_bcat[768];
__device__ __align__(128) float g_Chead[(size_t)3072 * 768];
__device__ unsigned g_bar;
__device__ unsigned g_snap;

__device__ __forceinline__ float ex2f(float x) {
    float y; asm("ex2.approx.ftz.f32 %0, %1;" : "=f"(y) : "f"(x)); return y;
}
__device__ __forceinline__ float sigmf(float x) {
    return 1.f / (1.f + ex2f(-x * LOG2E));
}
__device__ __forceinline__ float tanhf_f(float x) {
    x = fminf(fmaxf(x, -15.f), 15.f);
    float e = ex2f(-2.f * x * LOG2E);
    return (1.f - e) / (1.f + e);
}
__device__ __forceinline__ float4 add4(float4 a, const float* p) {
    float4 b = *(const float4*)p;
    a.x += b.x; a.y += b.y; a.z += b.z; a.w += b.w; return a;
}

// ---- img = x@Wb.T+bb -> k,v (one warp per output) ----
__global__ __launch_bounds__(256) void img_k(
    const float* __restrict__ xf, const float* __restrict__ Wb,
    const float* __restrict__ bb, const float* __restrict__ aiw,
    const float* __restrict__ aib)
{
    int gw = blockIdx.x * 8 + (threadIdx.x >> 5);
    int lane = threadIdx.x & 31;
    int b = gw >> 9, i = gw & 511;
    const float4* xr = (const float4*)(xf + (size_t)b * FEAT);
    const float4* wr = (const float4*)(Wb + (size_t)i * FEAT);
    float acc = 0.f;
#pragma unroll 4
    for (int m = 0; m < 16; ++m) {
        float4 a = xr[m * 32 + lane];
        float4 w = wr[m * 32 + lane];
        acc = fmaf(a.x, w.x, acc); acc = fmaf(a.y, w.y, acc);
        acc = fmaf(a.z, w.z, acc); acc = fmaf(a.w, w.w, acc);
    }
    for (int d = 16; d; d >>= 1) acc += __shfl_down_sync(0xffffffffu, acc, d);
    if (lane == 0) {
        acc += bb[i];
        g_k[b * 512 + i] = fmaf(acc, aiw[1], aib[1]);
        g_v[b * 512 + i] = fmaf(acc, aiw[2], aib[2]);
    }
}

// ---- per-batch k extrema + h0=0 + barrier snapshot ----
__global__ __launch_bounds__(512) void prep2_k()
{
    int blk = blockIdx.x, tid = threadIdx.x;
    if (blk < 32) {
        float v = g_k[blk * 512 + tid];
        float mn = v, mx = v;
        for (int d = 16; d; d >>= 1) {
            mn = fminf(mn, __shfl_down_sync(0xffffffffu, mn, d));
            mx = fmaxf(mx, __shfl_down_sync(0xffffffffu, mx, d));
        }
        __shared__ float smn[16], smx[16];
        if ((tid & 31) == 0) { smn[tid >> 5] = mn; smx[tid >> 5] = mx; }
        __syncthreads();
        if (tid == 0) {
            for (int w = 1; w < 16; ++w) { mn = fminf(mn, smn[w]); mx = fmaxf(mx, smx[w]); }
            g_kmin[blk] = mn; g_kmax[blk] = mx;
        }
    } else {
        for (int idx = tid; idx < BATCH * HDIM; idx += 512) g_h[idx] = 0.f;
        if (tid == 0) g_snap = g_bar;
    }
}

// ---- generic SGEMM: C[M,N] = A[M,K]@B[N,K]^T (+bias), BM128/BN64/BK16 ----
__global__ __launch_bounds__(256) void sgemm_nt(
    const float* __restrict__ A, int lda,
    const float* __restrict__ B, int ldb,
    const float* __restrict__ bias,
    float* __restrict__ C, int ldc, int M, int N, int K)
{
    __shared__ float As[16 * 132];
    __shared__ float Bs[16 * 68];
    int tid = threadIdx.x;
    int bm = blockIdx.y * 128, bn = blockIdx.x * 64;
    int tx = tid & 15, ty = tid >> 4;
    float acc[8][4];
#pragma unroll
    for (int i = 0; i < 8; ++i)
#pragma unroll
        for (int j = 0; j < 4; ++j) acc[i][j] = 0.f;
    int lr = tid >> 2, lk = (tid & 3) << 2;

    for (int kt = 0; kt < K; kt += 16) {
        float4 a0 = make_float4(0.f, 0.f, 0.f, 0.f), a1 = a0;
        int r0 = bm + lr, r1 = r0 + 64;
        if (r0 < M) a0 = *(const float4*)(A + (size_t)r0 * lda + kt + lk);
        if (r1 < M) a1 = *(const float4*)(A + (size_t)r1 * lda + kt + lk);
        float4 b0 = *(const float4*)(B + (size_t)(bn + lr) * ldb + kt + lk);
        __syncthreads();
        As[(lk + 0) * 132 + lr] = a0.x; As[(lk + 1) * 132 + lr] = a0.y;
        As[(lk + 2) * 132 + lr] = a0.z; As[(lk + 3) * 132 + lr] = a0.w;
        As[(lk + 0) * 132 + lr + 64] = a1.x; As[(lk + 1) * 132 + lr + 64] = a1.y;
        As[(lk + 2) * 132 + lr + 64] = a1.z; As[(lk + 3) * 132 + lr + 64] = a1.w;
        Bs[(lk + 0) * 68 + lr] = b0.x; Bs[(lk + 1) * 68 + lr] = b0.y;
        Bs[(lk + 2) * 68 + lr] = b0.z; Bs[(lk + 3) * 68 + lr] = b0.w;
        __syncthreads();
#pragma unroll
        for (int kk = 0; kk < 16; ++kk) {
            float ar[8], br[4];
            *(float4*)(ar)     = *(const float4*)&As[kk * 132 + ty * 8];
            *(float4*)(ar + 4) = *(const float4*)&As[kk * 132 + ty * 8 + 4];
            *(float4*)(br)     = *(const float4*)&Bs[kk * 68 + tx * 4];
#pragma unroll
            for (int i = 0; i < 8; ++i)
#pragma unroll
                for (int j = 0; j < 4; ++j)
                    acc[i][j] = fmaf(ar[i], br[j], acc[i][j]);
        }
    }
#pragma unroll
    for (int i = 0; i < 8; ++i) {
        int r = bm + ty * 8 + i;
        if (r < M) {
#pragma unroll
            for (int j = 0; j < 4; ++j) {
                int n = bn + tx * 4 + j;
                float v = acc[i][j];
                if (bias) v += bias[n];
                C[(size_t)r * ldc + n] = v;
            }
        }
    }
}

// ---- gi[t,b] = b_ih + Pclass[c] + sum Pbin_s[idx] ----
__global__ __launch_bounds__(384) void gather_k(
    const float* __restrict__ b_ih, const int* __restrict__ yc,
    const int* __restrict__ yx, const int* __restrict__ yy,
    const int* __restrict__ yw, const int* __restrict__ yh)
{
    int row = blockIdx.x;
    int t = row >> 5, b = row & 31;
    int c = 0, xi = 0, yi = 0, wi = 0, hi = 0;
    if (t > 0) {
        int o = b * T_STEPS + t - 1;
        c = yc[o]; xi = yx[o]; yi = yy[o]; wi = yw[o]; hi = yh[o];
    }
    int f = threadIdx.x << 2;
    float4 v = *(const float4*)(b_ih + f);
    v = add4(v, g_Pclass + (size_t)c * 1536 + f);
    v = add4(v, g_Pbin + ((size_t)0 * NBP + xi) * 1536 + f);
    v = add4(v, g_Pbin + ((size_t)1 * NBP + yi) * 1536 + f);
    v = add4(v, g_Pbin + ((size_t)2 * NBP + wi) * 1536 + f);
    v = add4(v, g_Pbin + ((size_t)3 * NBP + hi) * 1536 + f);
    *(float4*)(g_gi + (size_t)row * 1536 + f) = v;
}

// ---- pack head weights: Wc | Wp[0:452) | Wp[678:904) | Wd | zeros ----
__global__ __launch_bounds__(128) void pack_k(
    const float* __restrict__ Wc, const float* __restrict__ bc,
    const float* __restrict__ Wp, const float* __restrict__ bp,
    const float* __restrict__ Wd, const float* __restrict__ bd)
{
    int r = blockIdx.x;
    const float* src = nullptr; float bv = 0.f;
    if (r < 82)       { src = Wc + (size_t)r * 512;         bv = bc[r]; }
    else if (r < 534) { src = Wp + (size_t)(r - 82) * 512;  bv = bp[r - 82]; }
    else if (r < 760) { src = Wp + (size_t)(r + 144) * 512; bv = bp[r + 144]; }
    else if (r < 763) { src = Wd + (size_t)(r - 760) * 512; bv = bd[r - 760]; }
    int f = threadIdx.x << 2;
    float4 v = src ? *(const float4*)(src + f) : make_float4(0.f, 0.f, 0.f, 0.f);
    *(float4*)(g_Wcat + (size_t)r * 512 + f) = v;
    if (threadIdx.x == 0) g_bcat[r] = bv;
}

// ---- persistent scan kernel ----
#define SM_K   0
#define SM_V   16384
#define SM_H   32768      /* stride 36 per hidden index */
#define SM_W   51200      /* 12 rows x 512 */
#define SM_Q   57344
#define SM_KMN 57472
#define SM_KMX 57504
#define SM_BH  57536
#define SM_TOT 57548      /* floats -> 230192 bytes */

__global__ void __launch_bounds__(512, 1) scan_k(
    const float* __restrict__ W_hh, const float* __restrict__ b_hh,
    const float* __restrict__ aiw, const float* __restrict__ aib,
    const float* __restrict__ aow, const float* __restrict__ aob)
{
    extern __shared__ float sm[];
    const int tid = threadIdx.x;
    const int i0 = blockIdx.x * 4;
    const float aw0 = aiw[0], ab0 = aib[0];
    const float ow = aow[0], ob = aob[0];
    const unsigned snap = *(volatile unsigned*)&g_snap;

    for (int idx = tid; idx < 16384; idx += 512) {
        sm[SM_K + idx] = g_k[idx];
        sm[SM_V + idx] = g_v[idx];
    }
    for (int idx = tid; idx < 6144; idx += 512) {
        int lr = idx >> 9, k = idx & 511;   // lr = gate*4 + ii
        sm[SM_W + idx] = W_hh[(size_t)((lr >> 2) * 512 + i0 + (lr & 3)) * 512 + k];
    }
    if (tid < 12) sm[SM_BH + tid] = b_hh[(tid >> 2) * 512 + i0 + (tid & 3)];
    if (tid < 32) { sm[SM_KMN + tid] = g_kmin[tid]; sm[SM_KMX + tid] = g_kmax[tid]; }
    __syncthreads();

    const int ii_a = tid >> 5, bg = (tid >> 2) & 7, ks = tid & 3;   // phase A ids
    const int b_b = tid >> 4, ii_b = (tid >> 2) & 3, js = tid & 3;  // attention ids

    for (int t = 0; t < T_STEPS; ++t) {
        // load h_prev (other SMs wrote it) -> smem, stride-36 layout
        const float4* hsrc = (const float4*)(g_h + (t & 1) * 16384);
#pragma unroll
        for (int r = 0; r < 8; ++r) {
            int i4 = r * 512 + tid;
            float4 hv = __ldcg(hsrc + i4);
            int k = i4 >> 3, b0 = (i4 & 7) << 2;
            *(float4*)&sm[SM_H + k * 36 + b0] = hv;
        }
        __syncthreads();

        // phase A: gh = W_hh_slice @ h, GRU, q  (threads 0..127)
        if (tid < 128) {
            const int b = (bg << 2) | ks;
            const float* gp = g_gi + ((size_t)((t << 5) | b)) * 1536 + i0 + ii_a;
            float gir = __ldg(gp), giz = __ldg(gp + 512), gin = __ldg(gp + 1024);

            float a0[4] = {0.f,0.f,0.f,0.f}, a1[4] = {0.f,0.f,0.f,0.f}, a2[4] = {0.f,0.f,0.f,0.f};
            const float* wp = &sm[SM_W + ii_a * 512];
#pragma unroll 4
            for (int m = 0; m < 128; ++m) {
                int k = (m << 2) | ks;
                float4 hv = *(const float4*)&sm[SM_H + k * 36 + (bg << 2)];
                float w0 = wp[k], w1 = wp[2048 + k], w2 = wp[4096 + k];
                a0[0] = fmaf(w0, hv.x, a0[0]); a0[1] = fmaf(w0, hv.y, a0[1]);
                a0[2] = fmaf(w0, hv.z, a0[2]); a0[3] = fmaf(w0, hv.w, a0[3]);
                a1[0] = fmaf(w1, hv.x, a1[0]); a1[1] = fmaf(w1, hv.y, a1[1]);
                a1[2] = fmaf(w1, hv.z, a1[2]); a1[3] = fmaf(w1, hv.w, a1[3]);
                a2[0] = fmaf(w2, hv.x, a2[0]); a2[1] = fmaf(w2, hv.y, a2[1]);
                a2[2] = fmaf(w2, hv.z, a2[2]); a2[3] = fmaf(w2, hv.w, a2[3]);
            }
#pragma unroll
            for (int j = 0; j < 4; ++j) {
                a0[j] += __shfl_xor_sync(0xffffffffu, a0[j], 1, 4);
                a0[j] += __shfl_xor_sync(0xffffffffu, a0[j], 2, 4);
                a1[j] += __shfl_xor_sync(0xffffffffu, a1[j], 1, 4);
                a1[j] += __shfl_xor_sync(0xffffffffu, a1[j], 2, 4);
                a2[j] += __shfl_xor_sync(0xffffffffu, a2[j], 1, 4);
                a2[j] += __shfl_xor_sync(0xffffffffu, a2[j], 2, 4);
            }
            // this lane handles its own batch b (column ks of the reduced tile)
            float ghr = a0[ks] + sm[SM_BH + ii_a];
            float ghz = a1[ks] + sm[SM_BH + 4 + ii_a];
            float ghn = a2[ks] + sm[SM_BH + 8 + ii_a];
            float r_ = sigmf(gir + ghr);
            float z_ = sigmf(giz + ghz);
            float n_ = tanhf_f(fmaf(r_, ghn, gin));
            float hp = sm[SM_H + (i0 + ii_a) * 36 + b];
            float hg = fmaf(1.f - z_, n_, z_ * hp);
            sm[SM_Q + (ii_a << 5) + b] = fmaf(hg, aw0, ab0);
        }
        __syncthreads();

        // attention: rank-1 softmax over j (512), 4-way j-split per (b,i)
        {
            float q = sm[SM_Q + (ii_b << 5) + b_b];
            float mx = (q >= 0.f) ? q * sm[SM_KMX + b_b] : q * sm[SM_KMN + b_b];
            float ql = q * LOG2E, ml = mx * LOG2E;
            const float* kp = &sm[SM_K + (b_b << 9) + (js << 2)];
            const float* vp = &sm[SM_V + (b_b << 9) + (js << 2)];
            float se = 0.f, sv = 0.f;
#pragma unroll 4
            for (int m = 0; m < 32; ++m) {
                float4 kf = *(const float4*)(kp + (m << 4));
                float4 vf = *(const float4*)(vp + (m << 4));
                float e0 = ex2f(fmaf(ql, kf.x, -ml));
                float e1 = ex2f(fmaf(ql, kf.y, -ml));
                float e2 = ex2f(fmaf(ql, kf.z, -ml));
                float e3 = ex2f(fmaf(ql, kf.w, -ml));
                se += e0 + e1 + e2 + e3;
                sv = fmaf(e0, vf.x, sv); sv = fmaf(e1, vf.y, sv);
                sv = fmaf(e2, vf.z, sv); sv = fmaf(e3, vf.w, sv);
            }
            se += __shfl_xor_sync(0xffffffffu, se, 1, 4);
            se += __shfl_xor_sync(0xffffffffu, se, 2, 4);
            sv += __shfl_xor_sync(0xffffffffu, sv, 1, 4);
            sv += __shfl_xor_sync(0xffffffffu, sv, 2, 4);
            if (js == 0) {
                float hatt = fmaf(__fdividef(sv, se), ow, ob);
                int i = i0 + ii_b;
                g_Hall[(size_t)((t << 5) | b_b) * 512 + i] = hatt;
                if (t != T_STEPS - 1)
                    __stcg(&g_h[((t + 1) & 1) * 16384 + (i << 5) + b_b], hatt);
            }
        }

        if (t != T_STEPS - 1) {
            __syncthreads();
            if (tid == 0) {
                __threadfence();
                atomicAdd(&g_bar, 1u);
                unsigned target = snap + (unsigned)(t + 1) * NBLK;
                while ((int)(*(volatile unsigned*)&g_bar - target) < 0) { }
            }
            __syncthreads();
        }
    }
}

// ---- scatter heads to output (T,B)->(B,T), zero oh ----
__global__ __launch_bounds__(256) void scatter_k(float* __restrict__ out)
{
    int row = blockIdx.x;              // t*32 + b
    int t = row >> 5, b = row & 31;
    const float* src = g_Chead + (size_t)row * 768;
    int bt = b * 96 + t;
    for (int n = threadIdx.x; n < 226; n += 256) {
        if (n < 82) out[OFF_OC + (size_t)bt * 82 + n] = src[n];
        out[OFF_OX + (size_t)bt * 226 + n] = src[82 + n];
        out[OFF_OY + (size_t)bt * 226 + n] = src[308 + n];
        out[OFF_OW + (size_t)bt * 226 + n] = src[534 + n];
        out[OFF_OH + (size_t)bt * 226 + n] = 0.f;
        if (n < 3) out[OFF_OD + (size_t)bt * 3 + n] = src[760 + n];
    }
}

extern "C" void kernel_launch(void* const* d_in, const int* in_sizes, int n_in,
                              void* d_out, int out_size)
{
    const float* image_feat = (const float*)d_in[0];
    const int*   y_class    = (const int*)d_in[1];
    const int*   y_x        = (const int*)d_in[2];
    const int*   y_y        = (const int*)d_in[3];
    const int*   y_w        = (const int*)d_in[4];
    const int*   y_h        = (const int*)d_in[5];
    const float* class_emb  = (const float*)d_in[7];
    const float* bin_emb    = (const float*)d_in[8];
    const float* Wb         = (const float*)d_in[9];
    const float* bb         = (const float*)d_in[10];
    const float* W_ih       = (const float*)d_in[11];
    const float* b_ih       = (const float*)d_in[12];
    const float* W_hh       = (const float*)d_in[13];
    const float* b_hh       = (const float*)d_in[14];
    const float* aiw        = (const float*)d_in[15];
    const float* aib        = (const float*)d_in[16];
    const float* aow        = (const float*)d_in[17];
    const float* aob        = (const float*)d_in[18];
    const float* Wc         = (const float*)d_in[19];
    const float* bc         = (const float*)d_in[20];
    const float* Wp         = (const float*)d_in[21];
    const float* bp         = (const float*)d_in[22];
    const float* Wd         = (const float*)d_in[23];
    const float* bd         = (const float*)d_in[24];
    float* out = (float*)d_out;

    img_k<<<2048, 256>>>(image_feat, Wb, bb, aiw, aib);

    float* Pclass; cudaGetSymbolAddress((void**)&Pclass, g_Pclass);
    float* Pbin;   cudaGetSymbolAddress((void**)&Pbin, g_Pbin);
    float* Hall;   cudaGetSymbolAddress((void**)&Hall, g_Hall);
    float* Wcat;   cudaGetSymbolAddress((void**)&Wcat, g_Wcat);
    float* bcat;   cudaGetSymbolAddress((void**)&bcat, g_bcat);
    float* Chead;  cudaGetSymbolAddress((void**)&Chead, g_Chead);

    // embedding tables: P = emb @ W_ih_block^T
    sgemm_nt<<<dim3(24, 1), 256>>>(class_emb, 512, W_ih + 0, 2560, nullptr,
                                   Pclass, 1536, NCP, 1536, 512);
    for (int s = 0; s < 4; ++s)
        sgemm_nt<<<dim3(24, 2), 256>>>(bin_emb, 512, W_ih + 512 * (s + 1), 2560, nullptr,
                                       Pbin + (size_t)s * NBP * 1536, 1536, NBP, 1536, 512);

    gather_k<<<T_STEPS * BATCH, 384>>>(b_ih, y_class, y_x, y_y, y_w, y_h);
    prep2_k<<<33, 512>>>();
    pack_k<<<768, 128>>>(Wc, bc, Wp, bp, Wd, bd);

    cudaFuncSetAttribute(scan_k, cudaFuncAttributeMaxDynamicSharedMemorySize,
                         SM_TOT * sizeof(float));
    scan_k<<<NBLK, 512, SM_TOT * sizeof(float)>>>(W_hh, b_hh, aiw, aib, aow, aob);

    // heads: Chead = Hall(3072x512) @ Wcat(768x512)^T + bcat
    sgemm_nt<<<dim3(12, 24), 256>>>(Hall, 512, Wcat, 512, bcat, Chead, 768, 3072, 768, 512);

    scatter_k<<<T_STEPS * BATCH, 256>>>(out);
}